// round 2
// baseline (speedup 1.0000x reference)
#include <cuda_runtime.h>
#include <cuda_bf16.h>

// ConvQuadInterp3d: 27-point stencil keypoint refinement.
// x: (B=2, CH=1, D=10, H=512, W=512) fp32
// out: coords (B,1,3,D,H,W) then y_max (B,1,D,H,W), concatenated fp32.

#define Bb 2
#define Dd 10
#define Hh 512
#define Ww 512
#define TW 64
#define TH 4
#define SW (TW + 2)   // 66
#define SH (TH + 2)   // 6
#define NTHREADS (TW * TH)  // 256
#define SLICE_ELEMS (SH * SW)  // 396

__device__ __forceinline__ int clampi(int v, int lo, int hi) {
    return min(max(v, lo), hi);
}

__global__ __launch_bounds__(NTHREADS)
void cqi_kernel(const float* __restrict__ x, float* __restrict__ out)
{
    __shared__ float buf[3][SH][SW];

    const int w0 = blockIdx.x * TW;
    const int h0 = blockIdx.y * TH;
    const int b  = blockIdx.z;
    const int tx = threadIdx.x, ty = threadIdx.y;
    const int tid = ty * TW + tx;

    const size_t plane = (size_t)Hh * Ww;
    const float* xb = x + (size_t)b * Dd * plane;

    float* coords = out;
    float* ymax   = out + (size_t)Bb * 3 * Dd * plane;

    // Per-thread slice-load coordinates (constant across d)
    const int j0 = tid / SW, k0 = tid % SW;
    const int i1 = tid + NTHREADS;
    const int j1 = i1 / SW, k1 = i1 % SW;
    const bool has1 = (i1 < SLICE_ELEMS);
    const int off0 = clampi(h0 + j0 - 1, 0, Hh - 1) * Ww + clampi(w0 + k0 - 1, 0, Ww - 1);
    const int off1 = clampi(h0 + j1 - 1, 0, Hh - 1) * Ww + clampi(w0 + k1 - 1, 0, Ww - 1);

    // Prologue: load slices -1, 0, 1 (clamped) into buf[0], buf[1], buf[2]
    #pragma unroll
    for (int s = 0; s < 3; ++s) {
        const float* src = xb + (size_t)clampi(s - 1, 0, Dd - 1) * plane;
        buf[s][j0][k0] = __ldg(src + off0);
        if (has1) buf[s][j1][k1] = __ldg(src + off1);
    }

    float (*P)[SW] = buf[0];  // slice d-1
    float (*C)[SW] = buf[1];  // slice d
    float (*N)[SW] = buf[2];  // slice d+1

    const int h = h0 + ty;
    const int w = w0 + tx;

    #pragma unroll 1
    for (int d = 0; d < Dd; ++d) {
        // Prefetch slice d+2 into registers (overlaps with compute below)
        const float* src = xb + (size_t)clampi(d + 2, 0, Dd - 1) * plane;
        float r0 = __ldg(src + off0);
        float r1 = has1 ? __ldg(src + off1) : 0.0f;

        __syncthreads();  // smem slices for this d are ready

        // Load 3x3x3 neighborhood from smem
        const float v000 = P[ty  ][tx], v001 = P[ty  ][tx+1], v002 = P[ty  ][tx+2];
        const float v010 = P[ty+1][tx], v011 = P[ty+1][tx+1], v012 = P[ty+1][tx+2];
        const float v020 = P[ty+2][tx], v021 = P[ty+2][tx+1], v022 = P[ty+2][tx+2];
        const float v100 = C[ty  ][tx], v101 = C[ty  ][tx+1], v102 = C[ty  ][tx+2];
        const float v110 = C[ty+1][tx], v111 = C[ty+1][tx+1], v112 = C[ty+1][tx+2];
        const float v120 = C[ty+2][tx], v121 = C[ty+2][tx+1], v122 = C[ty+2][tx+2];
        const float v200 = N[ty  ][tx], v201 = N[ty  ][tx+1], v202 = N[ty  ][tx+2];
        const float v210 = N[ty+1][tx], v211 = N[ty+1][tx+1], v212 = N[ty+1][tx+2];
        const float v220 = N[ty+2][tx], v221 = N[ty+2][tx+1], v222 = N[ty+2][tx+2];

        const float cc = v111;

        // Max over 26 neighbors, then vs 0
        float nm;
        nm = fmaxf(v000, v001); nm = fmaxf(nm, v002);
        nm = fmaxf(nm, v010);   nm = fmaxf(nm, v011); nm = fmaxf(nm, v012);
        nm = fmaxf(nm, v020);   nm = fmaxf(nm, v021); nm = fmaxf(nm, v022);
        nm = fmaxf(nm, v100);   nm = fmaxf(nm, v101); nm = fmaxf(nm, v102);
        nm = fmaxf(nm, v110);                         nm = fmaxf(nm, v112);
        nm = fmaxf(nm, v120);   nm = fmaxf(nm, v121); nm = fmaxf(nm, v122);
        nm = fmaxf(nm, v200);   nm = fmaxf(nm, v201); nm = fmaxf(nm, v202);
        nm = fmaxf(nm, v210);   nm = fmaxf(nm, v211); nm = fmaxf(nm, v212);
        nm = fmaxf(nm, v220);   nm = fmaxf(nm, v221); nm = fmaxf(nm, v222);
        nm = fmaxf(nm, 0.0f);

        const bool m = (cc > nm);

        float dx0 = 0.0f, dx1 = 0.0f, dx2 = 0.0f;
        float gx = 0.0f, gy = 0.0f, gs = 0.0f;
        float yv = cc;

        // Warp fast path: skip solve if no lane is a maximum
        const unsigned ballot = __ballot_sync(0xFFFFFFFFu, m);
        if (ballot != 0u) {
            gx = 0.5f * (v112 - v110);
            gy = 0.5f * (v121 - v101);
            gs = 0.5f * (v211 - v011);
            const float dxx = v110 + v112 - 2.0f * cc;
            const float dyy = v101 + v121 - 2.0f * cc;
            const float dss = v011 + v211 - 2.0f * cc;
            const float dxy = 0.25f * (v100 + v122 - v120 - v102);
            const float dys = 0.25f * (v001 + v221 - v201 - v021);
            const float dxs = 0.25f * (v010 + v212 - v210 - v012);

            const float h00 = m ? dxx : 1.0f;
            const float h01 = m ? dxy : 0.0f;
            const float h02 = m ? dxs : 0.0f;
            const float h11 = m ? dyy : 1.0f;
            const float h12 = m ? dys : 0.0f;
            const float h22 = m ? dss : 1.0f;
            const float h10 = h01, h20 = h02, h21 = h12;
            const float b0 = m ? gx : 0.0f;
            const float b1 = m ? gy : 0.0f;
            const float b2 = m ? gs : 0.0f;

            const float c00 = h11 * h22 - h12 * h21;
            const float c01 = h10 * h22 - h12 * h20;
            const float c02 = h10 * h21 - h11 * h20;
            const float det = h00 * c00 - h01 * c01 + h02 * c02;
            const float inv = 1.0f / det;

            const float t0 = b1 * h22 - h12 * b2;
            const float t1 = b1 * h21 - h11 * b2;
            const float t2 = h10 * b2 - b1 * h20;

            const float sx = (b0 * c00 - h01 * t0 + h02 * t1) * inv;
            const float sy = (h00 * t0 - b0 * c01 + h02 * t2) * inv;
            const float ss = (h00 * (h11 * b2 - h21 * b1)
                            - h01 * (h10 * b2 - h20 * b1)
                            + b0 * c02) * inv;

            dx0 = -sx; dx1 = -sy; dx2 = -ss;
            const float mag = fmaxf(fmaxf(fabsf(dx0), fabsf(dx1)), fabsf(dx2));
            if (mag > 0.7f) { dx0 = 0.0f; dx1 = 0.0f; dx2 = 0.0f; }

            const float dy_ = 0.5f * (gx * dx0 + gy * dx1 + gs * dx2);
            yv = cc + dy_ + (m ? 10.0f : 0.0f);
        }

        // Outputs
        const size_t hw = (size_t)h * Ww + w;
        const size_t dplane = (size_t)d * plane + hw;
        const size_t cbase = (size_t)(b * 3) * Dd * plane;
        coords[cbase + 0 * Dd * plane + dplane] = (float)d + dx2;
        coords[cbase + 1 * Dd * plane + dplane] = (float)h + dx1;
        coords[cbase + 2 * Dd * plane + dplane] = (float)w + dx0;
        ymax[(size_t)b * Dd * plane + dplane] = yv;

        __syncthreads();  // compute done before overwriting oldest slice

        // Rotate buffers; store prefetched slice d+2 into the (now) next buffer
        float (*T)[SW] = P; P = C; C = N; N = T;
        N[j0][k0] = r0;
        if (has1) N[j1][k1] = r1;
    }
}

extern "C" void kernel_launch(void* const* d_in, const int* in_sizes, int n_in,
                              void* d_out, int out_size)
{
    const float* x = (const float*)d_in[0];
    float* out = (float*)d_out;
    dim3 grid(Ww / TW, Hh / TH, Bb);   // (8, 128, 2)
    dim3 block(TW, TH);                // (64, 4)
    cqi_kernel<<<grid, block>>>(x, out);
}